// round 6
// baseline (speedup 1.0000x reference)
#include <cuda_runtime.h>

#define NBLOCKS  1024
#define NTHREADS 256
// 1024 blocks <= 1184 resident CTAs -> single wave.
// Each thread handles 3 consecutive float4s (= 2 full 6-channel groups), so
// the channel pattern is compile-time uniform across all threads/lanes.
// groups = n4/3 = 2,097,152 = 262,144 threads * 8 iterations exactly.

__device__ float        g_pts[NBLOCKS];
__device__ float        g_prs[NBLOCKS];
__device__ unsigned int g_ctr = 0;   // reset by the last block each call

__device__ __forceinline__ float wrap_angle(float a) {
    const float PI  = 3.14159265358979323846f;
    const float TPI = 6.28318530717958647692f;
    a = (a >  PI) ? a - TPI : a;
    a = (a < -PI) ? a + TPI : a;
    return a;
}

__device__ __forceinline__ void rot_acc(float p, float t, float& rs) {
    float dw = wrap_angle(p) - wrap_angle(t);
    rs = fmaf(dw, dw, rs);
}
__device__ __forceinline__ void trans_acc(float p, float t, float& ts) {
    float d = p - t;
    ts = fmaf(d, d, ts);
}

__global__ void __launch_bounds__(NTHREADS)
wmse_kernel(const float4* __restrict__ p4, const float4* __restrict__ t4,
            unsigned n4, float* __restrict__ out) {
    const unsigned total   = NBLOCKS * NTHREADS;
    const unsigned tid     = blockIdx.x * NTHREADS + threadIdx.x;
    const unsigned ngroups = n4 / 3u;              // groups of 3 float4s

    float ts0 = 0.0f, ts1 = 0.0f, rs0 = 0.0f, rs1 = 0.0f;

    for (unsigned g = tid; g < ngroups; g += total) {
        unsigned v = g * 3u;
        float4 a0 = p4[v];
        float4 a1 = p4[v + 1u];
        float4 a2 = p4[v + 2u];
        float4 b0 = t4[v];
        float4 b1 = t4[v + 1u];
        float4 b2 = t4[v + 2u];

        // Channels: a0={0,1,2,3} a1={4,5,0,1} a2={2,3,4,5}
        trans_acc(a0.x, b0.x, ts0);   // ch0
        trans_acc(a0.y, b0.y, ts1);   // ch1
        trans_acc(a0.z, b0.z, ts0);   // ch2
        rot_acc  (a0.w, b0.w, rs0);   // ch3
        rot_acc  (a1.x, b1.x, rs1);   // ch4
        rot_acc  (a1.y, b1.y, rs0);   // ch5
        trans_acc(a1.z, b1.z, ts1);   // ch0
        trans_acc(a1.w, b1.w, ts0);   // ch1
        trans_acc(a2.x, b2.x, ts1);   // ch2
        rot_acc  (a2.y, b2.y, rs1);   // ch3
        rot_acc  (a2.z, b2.z, rs0);   // ch4
        rot_acc  (a2.w, b2.w, rs1);   // ch5
    }

    // Generic tail: leftover float4s when n4 % 3 != 0 (empty for bench shape).
    if (tid == 0) {
        const float* pf = (const float*)p4;
        const float* tf = (const float*)t4;
        for (unsigned v = ngroups * 3u; v < n4; v++) {
            #pragma unroll
            for (int j = 0; j < 4; j++) {
                unsigned c = (4u * v + (unsigned)j) % 6u;
                float p = pf[4u * v + j], t = tf[4u * v + j];
                if (c >= 3u) rot_acc(p, t, rs0);
                else         trans_acc(p, t, ts0);
            }
        }
    }

    float ts = ts0 + ts1;
    float rs = rs0 + rs1;

    // Block reduction
    #pragma unroll
    for (int o = 16; o > 0; o >>= 1) {
        ts += __shfl_xor_sync(0xffffffffu, ts, o);
        rs += __shfl_xor_sync(0xffffffffu, rs, o);
    }
    __shared__ float sts[NTHREADS / 32];
    __shared__ float srs[NTHREADS / 32];
    int lane = threadIdx.x & 31;
    int warp = threadIdx.x >> 5;
    if (lane == 0) { sts[warp] = ts; srs[warp] = rs; }
    __syncthreads();

    __shared__ bool isLast;
    if (threadIdx.x == 0) {
        float bts = 0.0f, brs = 0.0f;
        #pragma unroll
        for (int w = 0; w < NTHREADS / 32; w++) { bts += sts[w]; brs += srs[w]; }
        g_pts[blockIdx.x] = bts;
        g_prs[blockIdx.x] = brs;
        __threadfence();
        unsigned prev = atomicAdd(&g_ctr, 1u);
        isLast = (prev == (unsigned)gridDim.x - 1u);
    }
    __syncthreads();

    if (isLast) {
        __threadfence();
        float a = 0.0f, b = 0.0f;
        for (unsigned i = threadIdx.x; i < NBLOCKS; i += NTHREADS) {
            a += g_pts[i];
            b += g_prs[i];
        }
        #pragma unroll
        for (int o = 16; o > 0; o >>= 1) {
            a += __shfl_xor_sync(0xffffffffu, a, o);
            b += __shfl_xor_sync(0xffffffffu, b, o);
        }
        __syncthreads();                 // sts/srs reuse
        if (lane == 0) { sts[warp] = a; srs[warp] = b; }
        __syncthreads();
        if (threadIdx.x == 0) {
            float A = 0.0f, B = 0.0f;
            #pragma unroll
            for (int w = 0; w < NTHREADS / 32; w++) { A += sts[w]; B += srs[w]; }
            g_ctr = 0;                   // rearm for the next graph replay
            double cnt        = 2.0 * (double)n4;           // elems / 2
            double trans_loss = (double)A / cnt;            // TRANS_WEIGHT=1
            double rot_loss   = ((double)B / cnt) * 100.0;  // ROT_WEIGHT=100
            out[0] = (float)(trans_loss + rot_loss);
            out[1] = (float)trans_loss;
            out[2] = (float)rot_loss;
        }
    }
}

extern "C" void kernel_launch(void* const* d_in, const int* in_sizes, int n_in,
                              void* d_out, int out_size) {
    const float4* pred4   = (const float4*)d_in[0];
    const float4* target4 = (const float4*)d_in[1];
    unsigned n4 = (unsigned)(in_sizes[0] / 4);

    wmse_kernel<<<NBLOCKS, NTHREADS>>>(pred4, target4, n4, (float*)d_out);
}

// round 7
// speedup vs baseline: 1.0125x; 1.0125x over previous
#include <cuda_runtime.h>

#define NBLOCKS  1182
#define NTHREADS 256
// 1182 = 2*3*197 -> total = 302,592 threads divisible by 3 (v%3 per-thread const)
// 1182 <= 1184 resident CTAs: single wave, 146/148 SMs at full 8 CTAs.

__device__ float        g_ptot[NBLOCKS];
__device__ float        g_prs[NBLOCKS];
__device__ unsigned int g_ctr = 0;   // reset by the last block each call

#define PI_F  3.14159265358979323846f
#define TPI_F 6.28318530717958647692f

// corr(x) = -2pi if x > pi, +2pi if x < -pi, else 0
// (|x| > pi) ? -copysign(2pi, x) : 0   -> FSETP(|x|) + LOP3 + FSEL
__device__ __forceinline__ float wrap_corr(float x) {
    return (fabsf(x) > PI_F) ? -copysignf(TPI_F, x) : 0.0f;
}

__global__ void __launch_bounds__(NTHREADS)
wmse_kernel(const float4* __restrict__ p4, const float4* __restrict__ t4,
            unsigned n4, float* __restrict__ out) {
    const unsigned total = NBLOCKS * NTHREADS;     // divisible by 3
    const unsigned tid   = blockIdx.x * NTHREADS + threadIdx.x;

    // Rotation-lane pattern of float4 #v depends only on v % 3 == tid % 3:
    //   m=0 -> channels {0,1,2,3} -> rot lanes {w}
    //   m=1 -> channels {4,5,0,1} -> rot lanes {x,y}
    //   m=2 -> channels {2,3,4,5} -> rot lanes {y,z,w}
    const unsigned m = tid % 3u;
    float4 rw;                                      // 1.0 where rotation lane
    rw.x = (m == 1u) ? 1.0f : 0.0f;
    rw.y = (m != 0u) ? 1.0f : 0.0f;
    rw.z = (m == 2u) ? 1.0f : 0.0f;
    rw.w = (m != 1u) ? 1.0f : 0.0f;

    float tot = 0.0f;   // sum of val^2 over ALL lanes
    float rs  = 0.0f;   // sum of val^2 over rotation lanes only

    for (unsigned v = tid; v < n4; v += total) {
        float4 p = p4[v];
        float4 t = t4[v];

        // plain diffs (shared by both paths)
        float dx = p.x - t.x, dy = p.y - t.y, dz = p.z - t.z, dw = p.w - t.w;

        // wrap-correction deltas
        float cx = wrap_corr(p.x) - wrap_corr(t.x);
        float cy = wrap_corr(p.y) - wrap_corr(t.y);
        float cz = wrap_corr(p.z) - wrap_corr(t.z);
        float cw = wrap_corr(p.w) - wrap_corr(t.w);

        // val = d on trans lanes (w=0), wrapped diff on rot lanes (w=1)
        float vx = fmaf(rw.x, cx, dx);
        float vy = fmaf(rw.y, cy, dy);
        float vz = fmaf(rw.z, cz, dz);
        float vw = fmaf(rw.w, cw, dw);

        float qx = vx * vx, qy = vy * vy, qz = vz * vz, qw = vw * vw;
        tot += qx; tot += qy; tot += qz; tot += qw;
        rs = fmaf(qx, rw.x, rs);
        rs = fmaf(qy, rw.y, rs);
        rs = fmaf(qz, rw.z, rs);
        rs = fmaf(qw, rw.w, rs);
    }

    // Block reduction of (tot, rs)
    #pragma unroll
    for (int o = 16; o > 0; o >>= 1) {
        tot += __shfl_xor_sync(0xffffffffu, tot, o);
        rs  += __shfl_xor_sync(0xffffffffu, rs, o);
    }
    __shared__ float stot[NTHREADS / 32];
    __shared__ float srs[NTHREADS / 32];
    int lane = threadIdx.x & 31;
    int warp = threadIdx.x >> 5;
    if (lane == 0) { stot[warp] = tot; srs[warp] = rs; }
    __syncthreads();

    __shared__ bool isLast;
    if (threadIdx.x == 0) {
        float btot = 0.0f, brs = 0.0f;
        #pragma unroll
        for (int w = 0; w < NTHREADS / 32; w++) { btot += stot[w]; brs += srs[w]; }
        g_ptot[blockIdx.x] = btot;
        g_prs[blockIdx.x]  = brs;
        __threadfence();
        unsigned prev = atomicAdd(&g_ctr, 1u);
        isLast = (prev == (unsigned)gridDim.x - 1u);
    }
    __syncthreads();

    if (isLast) {
        __threadfence();
        float a = 0.0f, b = 0.0f;
        for (unsigned i = threadIdx.x; i < NBLOCKS; i += NTHREADS) {
            a += g_ptot[i];
            b += g_prs[i];
        }
        #pragma unroll
        for (int o = 16; o > 0; o >>= 1) {
            a += __shfl_xor_sync(0xffffffffu, a, o);
            b += __shfl_xor_sync(0xffffffffu, b, o);
        }
        __syncthreads();                 // stot/srs reuse
        if (lane == 0) { stot[warp] = a; srs[warp] = b; }
        __syncthreads();
        if (threadIdx.x == 0) {
            float A = 0.0f, B = 0.0f;    // A = tot sum, B = rot sum
            #pragma unroll
            for (int w = 0; w < NTHREADS / 32; w++) { A += stot[w]; B += srs[w]; }
            g_ctr = 0;                   // rearm for the next graph replay
            double cnt        = 2.0 * (double)n4;            // elems / 2
            double rot_sum    = (double)B;
            double trans_sum  = (double)A - rot_sum;         // tot - rot
            double trans_loss = trans_sum / cnt;             // TRANS_WEIGHT=1
            double rot_loss   = (rot_sum / cnt) * 100.0;     // ROT_WEIGHT=100
            out[0] = (float)(trans_loss + rot_loss);
            out[1] = (float)trans_loss;
            out[2] = (float)rot_loss;
        }
    }
}

extern "C" void kernel_launch(void* const* d_in, const int* in_sizes, int n_in,
                              void* d_out, int out_size) {
    const float4* pred4   = (const float4*)d_in[0];
    const float4* target4 = (const float4*)d_in[1];
    unsigned n4 = (unsigned)(in_sizes[0] / 4);

    wmse_kernel<<<NBLOCKS, NTHREADS>>>(pred4, target4, n4, (float*)d_out);
}

// round 8
// speedup vs baseline: 1.0546x; 1.0416x over previous
#include <cuda_runtime.h>

#define NBLOCKS  888
#define NTHREADS 256
// 888 = 6 CTAs/SM x 148 SMs -> exactly one resident wave at 256 threads.
// Register budget 65536/1536 = 42 regs/thread: room for 2x 256-bit loads in
// flight + 8 weight regs without spills.
// total = 227,328 threads, divisible by 3 -> chunk%3 loop-invariant per thread.

__device__ float        g_ptot[NBLOCKS];
__device__ float        g_prs[NBLOCKS];
__device__ unsigned int g_ctr = 0;   // reset by the last block each call

#define PI_F  3.14159265358979323846f
#define TPI_F 6.28318530717958647692f

// corr(x) = -2pi if x > pi, +2pi if x < -pi, else 0  (single-step wrap delta)
__device__ __forceinline__ float wrap_corr(float x) {
    return (fabsf(x) > PI_F) ? -copysignf(TPI_F, x) : 0.0f;
}

// Blackwell 256-bit global load: 8 consecutive floats per thread.
__device__ __forceinline__ void ldg256(const float* __restrict__ p, float* r) {
    asm("ld.global.nc.v8.f32 {%0,%1,%2,%3,%4,%5,%6,%7}, [%8];"
        : "=f"(r[0]), "=f"(r[1]), "=f"(r[2]), "=f"(r[3]),
          "=f"(r[4]), "=f"(r[5]), "=f"(r[6]), "=f"(r[7])
        : "l"(p));
}

__global__ void __launch_bounds__(NTHREADS, 6)
wmse_kernel(const float* __restrict__ pf, const float* __restrict__ tf,
            unsigned n, float* __restrict__ out) {
    const unsigned total = NBLOCKS * NTHREADS;     // divisible by 3
    const unsigned tid   = blockIdx.x * NTHREADS + threadIdx.x;
    const unsigned n8    = n / 8u;                 // 8-float chunks

    // Channels of chunk u are (8u..8u+7) mod 6; pattern depends only on
    // u % 3 == tid % 3 (stride divisible by 3):
    //   m=0 -> rot lanes {3,4,5}
    //   m=1 -> rot lanes {1,2,3,7}
    //   m=2 -> rot lanes {0,1,5,6,7}
    const unsigned m = tid % 3u;
    float w[8];
    w[0] = (m == 2u) ? 1.0f : 0.0f;
    w[1] = (m != 0u) ? 1.0f : 0.0f;
    w[2] = (m == 1u) ? 1.0f : 0.0f;
    w[3] = (m != 2u) ? 1.0f : 0.0f;
    w[4] = (m == 0u) ? 1.0f : 0.0f;
    w[5] = (m != 1u) ? 1.0f : 0.0f;
    w[6] = (m == 2u) ? 1.0f : 0.0f;
    w[7] = (m != 0u) ? 1.0f : 0.0f;

    float tot = 0.0f;   // sum of val^2 over ALL lanes
    float rs  = 0.0f;   // sum of val^2 over rotation lanes only

    for (unsigned u = tid; u < n8; u += total) {
        float P[8], T[8];
        ldg256(pf + (size_t)u * 8u, P);
        ldg256(tf + (size_t)u * 8u, T);

        #pragma unroll
        for (int i = 0; i < 8; i++) {
            float d  = P[i] - T[i];
            float cd = wrap_corr(P[i]) - wrap_corr(T[i]);
            float v  = fmaf(w[i], cd, d);  // trans: d, rot: wrapped diff
            float q  = v * v;
            tot += q;
            rs  = fmaf(q, w[i], rs);
        }
    }

    // Generic tail: floats beyond the last full 8-chunk (empty for bench shape).
    if (tid == 0) {
        for (unsigned f = n8 * 8u; f < n; f++) {
            unsigned c = f % 6u;
            float d  = pf[f] - tf[f];
            float cd = wrap_corr(pf[f]) - wrap_corr(tf[f]);
            float v  = (c >= 3u) ? (d + cd) : d;
            float q  = v * v;
            tot += q;
            if (c >= 3u) rs += q;
        }
    }

    // Block reduction of (tot, rs)
    #pragma unroll
    for (int o = 16; o > 0; o >>= 1) {
        tot += __shfl_xor_sync(0xffffffffu, tot, o);
        rs  += __shfl_xor_sync(0xffffffffu, rs, o);
    }
    __shared__ float stot[NTHREADS / 32];
    __shared__ float srs[NTHREADS / 32];
    int lane = threadIdx.x & 31;
    int warp = threadIdx.x >> 5;
    if (lane == 0) { stot[warp] = tot; srs[warp] = rs; }
    __syncthreads();

    __shared__ bool isLast;
    if (threadIdx.x == 0) {
        float btot = 0.0f, brs = 0.0f;
        #pragma unroll
        for (int ww = 0; ww < NTHREADS / 32; ww++) { btot += stot[ww]; brs += srs[ww]; }
        g_ptot[blockIdx.x] = btot;
        g_prs[blockIdx.x]  = brs;
        __threadfence();
        unsigned prev = atomicAdd(&g_ctr, 1u);
        isLast = (prev == (unsigned)gridDim.x - 1u);
    }
    __syncthreads();

    if (isLast) {
        __threadfence();
        float a = 0.0f, b = 0.0f;
        for (unsigned i = threadIdx.x; i < NBLOCKS; i += NTHREADS) {
            a += g_ptot[i];
            b += g_prs[i];
        }
        #pragma unroll
        for (int o = 16; o > 0; o >>= 1) {
            a += __shfl_xor_sync(0xffffffffu, a, o);
            b += __shfl_xor_sync(0xffffffffu, b, o);
        }
        __syncthreads();                 // stot/srs reuse
        if (lane == 0) { stot[warp] = a; srs[warp] = b; }
        __syncthreads();
        if (threadIdx.x == 0) {
            float A = 0.0f, B = 0.0f;    // A = tot sum, B = rot sum
            #pragma unroll
            for (int ww = 0; ww < NTHREADS / 32; ww++) { A += stot[ww]; B += srs[ww]; }
            g_ctr = 0;                   // rearm for the next graph replay
            double cnt        = (double)n * 0.5;             // elems / 2
            double rot_sum    = (double)B;
            double trans_sum  = (double)A - rot_sum;         // tot - rot
            double trans_loss = trans_sum / cnt;             // TRANS_WEIGHT=1
            double rot_loss   = (rot_sum / cnt) * 100.0;     // ROT_WEIGHT=100
            out[0] = (float)(trans_loss + rot_loss);
            out[1] = (float)trans_loss;
            out[2] = (float)rot_loss;
        }
    }
}

extern "C" void kernel_launch(void* const* d_in, const int* in_sizes, int n_in,
                              void* d_out, int out_size) {
    const float* pred   = (const float*)d_in[0];
    const float* target = (const float*)d_in[1];
    unsigned n = (unsigned)in_sizes[0];

    wmse_kernel<<<NBLOCKS, NTHREADS>>>(pred, target, n, (float*)d_out);
}